// round 1
// baseline (speedup 1.0000x reference)
#include <cuda_runtime.h>

#define BB 128
#define MM 60
#define FG 19
#define NAk 3
#define NCc 80
#define NCELL (BB*NAk*FG*FG)   // 138624

__device__ double g_acc[6];
__device__ int    g_flag[NCELL];
__device__ float  g_payload[NCELL][8];
__device__ float  g_truth[BB][MM][8];

// anchors / 32 (exact in fp32)
__constant__ float c_aw[9] = {0.3125f, 0.5f,     1.03125f, 0.9375f, 1.9375f,
                              1.84375f, 3.625f,  4.875f,   11.65625f};
__constant__ float c_ah[9] = {0.40625f, 0.9375f, 0.71875f, 1.90625f, 1.40625f,
                              3.71875f, 2.8125f, 6.1875f,  10.1875f};

__global__ void k_init() {
    int i = blockIdx.x * blockDim.x + threadIdx.x;
    if (i < NCELL) g_flag[i] = 0;
    if (i < 6) g_acc[i] = 0.0;
}

// One thread per batch: serial over m (last label wins on duplicate cells,
// matching XLA's in-order scatter-set).
__global__ void __launch_bounds__(128) k_scatter(const float* __restrict__ labels) {
    int b = threadIdx.x;
    if (b >= BB) return;
    for (int m = 0; m < MM; m++) {
        const float* L = labels + (b * MM + m) * 5;
        float l0 = L[0], l1 = L[1], l2 = L[2], l3 = L[3], l4 = L[4];
        bool valid = (l0 + l1 + l2 + l3 + l4) > 0.0f;
        float tx = floorf(l0 * 0.03125f);
        float ty = floorf(l1 * 0.03125f);
        float tw = floorf((l2 - l0) * 0.03125f);
        float th = floorf((l3 - l1) * 0.03125f);
        float ta = tw * th;

        // truth box corners + area for the ignore-mask IoU pass
        float* T = &g_truth[b][m][0];
        if (valid) {
            float hw = tw * 0.5f, hh = th * 0.5f;
            T[0] = tx - hw; T[1] = ty - hh; T[2] = tx + hw; T[3] = ty + hh; T[4] = ta;
        } else {
            // degenerate far-away box -> zero intersection -> iou 0
            T[0] = 3e18f; T[1] = 3e18f; T[2] = 3e18f; T[3] = 3e18f; T[4] = 0.f;
        }
        T[5] = 0.f; T[6] = 0.f; T[7] = 0.f;

        // anchor matching: argmax (first max wins) over 9 reference anchors
        float best = -1.0f; int bi = 0;
        #pragma unroll
        for (int k = 0; k < 9; k++) {
            float mw = fminf(tw, c_aw[k]);
            float mh = fminf(th, c_ah[k]);
            float inter = (mw > 0.f && mh > 0.f) ? mw * mh : 0.f;
            float aiou = inter / (ta + c_aw[k] * c_ah[k] - inter);
            if (aiou > best) { best = aiou; bi = k; }
        }

        if (valid && bi >= 6) {
            int bn = bi - 6;                 // best_all % 3 (since bi>=6)
            int ti = (int)tx, tj = (int)ty;  // int32 cast (trunc), as reference
            long flat = (((long)b * 3 + bn) * FG + tj) * FG + ti;
            if (flat >= 0 && flat < NCELL) { // mode='drop' semantics
                float txf = tx - (float)((int)tx);
                float tyf = ty - (float)((int)ty);
                float twt = logf(tw / c_aw[6 + bn] + 1e-16f);
                float tht = logf(th / c_ah[6 + bn] + 1e-16f);
                float sc  = sqrtf(2.0f - ta / 361.0f);
                g_flag[flat] = 1;
                float* P = &g_payload[flat][0];
                P[0] = txf; P[1] = tyf; P[2] = twt; P[3] = tht; P[4] = sc; P[5] = l4;
                P[6] = 0.f; P[7] = 0.f;
            }
        }
    }
}

// One thread per (b, j, i); all 3 anchors held in registers so the 60-truth
// IoU loop amortizes the shared-memory truth loads 3x.
__global__ void __launch_bounds__(128) k_main(const float* __restrict__ out) {
    int b = blockIdx.y;
    __shared__ __align__(16) float sT[MM * 8];
    for (int t = threadIdx.x; t < MM * 2; t += blockDim.x)
        ((float4*)sT)[t] = ((const float4*)&g_truth[b][0][0])[t];
    __syncthreads();

    int idx = blockIdx.x * blockDim.x + threadIdx.x;  // 0..383, 361 valid
    float a_xy = 0.f, a_wh = 0.f, a_obj = 0.f, a_cls = 0.f, a_l2 = 0.f;

    if (idx < FG * FG) {
        int j = idx / FG, i = idx - j * FG;
        const float caw[3] = {3.625f, 4.875f, 11.65625f};
        const float cah[3] = {2.8125f, 6.1875f, 10.1875f};
        float sx[3], sy[3], zw[3], zh[3], zo[3];
        float ax1[3], ay1[3], ax2[3], ay2[3], pA[3], dd[3];

        #pragma unroll
        for (int a = 0; a < 3; a++) {
            long base = (((long)b * 255 + a * 85) * 361) + idx;
            float x0 = __ldg(&out[base]);
            float y0 = __ldg(&out[base + 361]);
            zw[a] = __ldg(&out[base + 722]);
            zh[a] = __ldg(&out[base + 1083]);
            zo[a] = __ldg(&out[base + 1444]);
            sx[a] = 1.f / (1.f + __expf(-x0));
            sy[a] = 1.f / (1.f + __expf(-y0));
            float pw = __expf(zw[a]) * caw[a];
            float ph = __expf(zh[a]) * cah[a];
            float px = sx[a] + (float)i;
            float py = sy[a] + (float)j;
            ax1[a] = px - 0.5f * pw; ax2[a] = px + 0.5f * pw;
            ay1[a] = py - 0.5f * ph; ay2[a] = py + 0.5f * ph;
            pA[a] = pw * ph;
            dd[a] = -1e30f;   // max_m(3*inter - (pA+bA)) <= 0  <=>  best_iou <= 0.5
        }

        #pragma unroll 4
        for (int m = 0; m < MM; m++) {
            float4 c = ((const float4*)sT)[m * 2];   // bx1,by1,bx2,by2
            float bA = sT[m * 8 + 4];
            #pragma unroll
            for (int a = 0; a < 3; a++) {
                float w = fminf(ax2[a], c.z) - fmaxf(ax1[a], c.x);
                float h = fminf(ay2[a], c.w) - fmaxf(ay1[a], c.y);
                float inter = fmaxf(w, 0.f) * fmaxf(h, 0.f);
                dd[a] = fmaxf(dd[a], __fmaf_rn(inter, 3.f, -(pA[a] + bA)));
            }
        }

        #pragma unroll
        for (int a = 0; a < 3; a++) {
            int flat = ((b * 3 + a) * FG + j) * FG + i;
            bool matched = (g_flag[flat] != 0);
            float so = 1.f / (1.f + __expf(-zo[a]));
            if (matched) {
                const float* P = &g_payload[flat][0];
                float4 p0 = *(const float4*)P;
                float txf = p0.x, tyf = p0.y, twt = p0.z, tht = p0.w;
                float sc = P[4]; int cls = (int)P[5];
                float w2 = sc * sc;
                float lpx = fmaxf(__logf(sx[a]), -100.f);
                float lqx = fmaxf(__logf(1.f - sx[a]), -100.f);
                float lpy = fmaxf(__logf(sy[a]), -100.f);
                float lqy = fmaxf(__logf(1.f - sy[a]), -100.f);
                a_xy += -w2 * (txf * lpx + (1.f - txf) * lqx)
                        - w2 * (tyf * lpy + (1.f - tyf) * lqy);
                float dw = zw[a] - twt, dh = zh[a] - tht;
                float whs = w2 * (dw * dw + dh * dh);
                a_wh += 0.5f * whs;
                a_obj += -fmaxf(__logf(so), -100.f);       // t=1 at matched cells
                float ex = sx[a] - txf, ey = sy[a] - tyf, eo = so - 1.f;
                a_l2 += ex * ex + ey * ey + whs + eo * eo;
                long cbase = (((long)b * 255 + a * 85 + 5) * 361) + idx;
                for (int cc = 0; cc < NCc; cc++) {
                    float z = __ldg(&out[cbase + (long)cc * 361]);
                    float p = 1.f / (1.f + __expf(-z));
                    float lp = fmaxf(__logf(p), -100.f);
                    float lq = fmaxf(__logf(1.f - p), -100.f);
                    float t = (cc == cls) ? 1.f : 0.f;
                    a_cls += -(t * lp + (1.f - t) * lq);
                    float e = p - t;
                    a_l2 += e * e;
                }
            } else if (dd[a] <= 0.f) {   // obj_mask=1, t=0
                a_obj += -fmaxf(__logf(1.f - so), -100.f);
                a_l2 += so * so;
            }
            // else: ignored cell, contributes nothing
        }
    }

    // warp reduce then double atomics (384 blocks * 4 warps * 5 atomics)
    unsigned m = 0xffffffffu;
    for (int off = 16; off > 0; off >>= 1) {
        a_xy  += __shfl_down_sync(m, a_xy, off);
        a_wh  += __shfl_down_sync(m, a_wh, off);
        a_obj += __shfl_down_sync(m, a_obj, off);
        a_cls += __shfl_down_sync(m, a_cls, off);
        a_l2  += __shfl_down_sync(m, a_l2, off);
    }
    if ((threadIdx.x & 31) == 0) {
        atomicAdd(&g_acc[1], (double)a_xy);
        atomicAdd(&g_acc[2], (double)a_wh);
        atomicAdd(&g_acc[3], (double)a_obj);
        atomicAdd(&g_acc[4], (double)a_cls);
        atomicAdd(&g_acc[5], (double)a_l2);
    }
}

__global__ void k_final(float* o) {
    double xy = g_acc[1], wh = g_acc[2], ob = g_acc[3], cl = g_acc[4], l2 = g_acc[5];
    o[0] = (float)(xy + wh + ob + cl);
    o[1] = (float)xy;
    o[2] = (float)wh;
    o[3] = (float)ob;
    o[4] = (float)cl;
    o[5] = (float)l2;
}

extern "C" void kernel_launch(void* const* d_in, const int* in_sizes, int n_in,
                              void* d_out, int out_size) {
    const float* output = (const float*)d_in[0];
    const float* labels = (const float*)d_in[1];
    float* o = (float*)d_out;
    (void)in_sizes; (void)n_in; (void)out_size;

    k_init<<<(NCELL + 255) / 256, 256>>>();
    k_scatter<<<1, 128>>>(labels);
    dim3 g(3, BB);
    k_main<<<g, 128>>>(output);
    k_final<<<1, 1>>>(o);
}

// round 2
// speedup vs baseline: 1.8585x; 1.8585x over previous
#include <cuda_runtime.h>

#define BB 128
#define MM 60
#define FG 19
#define NCc 80
#define NCELL (BB*3*FG*FG)   // 138624

__device__ double g_acc[6];
__device__ int    g_flag[NCELL];
__device__ float  g_payload[NCELL][8];
__device__ float  g_truth[BB][MM][8];
__device__ int    g_mlist[BB*MM];
__device__ int    g_nmatch;
__device__ int    g_done;

// anchors / 32 (exact in fp32)
__constant__ float c_aw[9] = {0.3125f, 0.5f,     1.03125f, 0.9375f, 1.9375f,
                              1.84375f, 3.625f,  4.875f,   11.65625f};
__constant__ float c_ah[9] = {0.40625f, 0.9375f, 0.71875f, 1.90625f, 1.40625f,
                              3.71875f, 2.8125f, 6.1875f,  10.1875f};

// Block per batch: coalesced label load, per-label math in parallel,
// single-thread in-order commit (last-label-wins on duplicate cells) that
// also builds the compacted matched-cell list.
__global__ void __launch_bounds__(64) k_scatter(const float* __restrict__ labels) {
    int b = blockIdx.x;
    __shared__ float sL[MM * 5];
    __shared__ float sPay[MM][6];
    __shared__ int   sFlat[MM];

    if (b == 0 && threadIdx.x < 6) g_acc[threadIdx.x] = 0.0;

    for (int t = threadIdx.x; t < MM * 5; t += 64)
        sL[t] = labels[b * (MM * 5) + t];
    __syncthreads();

    int m = threadIdx.x;
    if (m < MM) {
        float l0 = sL[m*5], l1 = sL[m*5+1], l2 = sL[m*5+2], l3 = sL[m*5+3], l4 = sL[m*5+4];
        bool valid = (l0 + l1 + l2 + l3 + l4) > 0.0f;
        float tx = floorf(l0 * 0.03125f);
        float ty = floorf(l1 * 0.03125f);
        float tw = floorf((l2 - l0) * 0.03125f);
        float th = floorf((l3 - l1) * 0.03125f);
        float ta = tw * th;

        float* T = &g_truth[b][m][0];
        if (valid) {
            float hw = tw * 0.5f, hh = th * 0.5f;
            T[0] = tx - hw; T[1] = ty - hh; T[2] = tx + hw; T[3] = ty + hh; T[4] = ta;
        } else {
            T[0] = 3e18f; T[1] = 3e18f; T[2] = 3e18f; T[3] = 3e18f; T[4] = 0.f;
        }

        float best = -1.0f; int bi = 0;
        #pragma unroll
        for (int k = 0; k < 9; k++) {
            float mw = fminf(tw, c_aw[k]);
            float mh = fminf(th, c_ah[k]);
            float inter = (mw > 0.f && mh > 0.f) ? mw * mh : 0.f;
            float aiou = inter / (ta + c_aw[k] * c_ah[k] - inter);
            if (aiou > best) { best = aiou; bi = k; }
        }

        int flat = -1;
        if (valid && bi >= 6) {
            int bn = bi - 6;
            int ti = (int)tx, tj = (int)ty;
            long f = (((long)b * 3 + bn) * FG + tj) * FG + ti;
            if (f >= 0 && f < NCELL && ti >= 0 && ti < FG && tj >= 0 && tj < FG) {
                flat = (int)f;
                sPay[m][0] = tx - (float)((int)tx);
                sPay[m][1] = ty - (float)((int)ty);
                sPay[m][2] = logf(tw / c_aw[6 + bn] + 1e-16f);
                sPay[m][3] = logf(th / c_ah[6 + bn] + 1e-16f);
                sPay[m][4] = sqrtf(2.0f - ta / 361.0f);
                sPay[m][5] = l4;
            }
        }
        sFlat[m] = flat;
    }
    __syncthreads();

    if (threadIdx.x == 0) {
        for (int mm = 0; mm < MM; mm++) {
            int f = sFlat[mm];
            if (f >= 0) {
                if (g_flag[f] == 0) {
                    g_flag[f] = 1;
                    int p = atomicAdd(&g_nmatch, 1);
                    g_mlist[p] = f;
                }
                #pragma unroll
                for (int q = 0; q < 6; q++) g_payload[f][q] = sPay[mm][q];
            }
        }
    }
}

// One thread per (b, j, i); 3 anchors in registers; ignore-mask IoU pass +
// xy/wh/obj losses. Class loss handled in k_cls.
__global__ void __launch_bounds__(128) k_main(const float* __restrict__ out) {
    int b = blockIdx.y;
    __shared__ __align__(16) float sT[MM * 8];
    for (int t = threadIdx.x; t < MM * 2; t += blockDim.x)
        ((float4*)sT)[t] = ((const float4*)&g_truth[b][0][0])[t];
    __syncthreads();

    int idx = blockIdx.x * blockDim.x + threadIdx.x;
    float a_xy = 0.f, a_wh = 0.f, a_obj = 0.f, a_l2 = 0.f;

    if (idx < FG * FG) {
        int j = idx / FG, i = idx - j * FG;
        const float caw[3] = {3.625f, 4.875f, 11.65625f};
        const float cah[3] = {2.8125f, 6.1875f, 10.1875f};
        float sx[3], sy[3], zw[3], zh[3], zo[3];
        float ax1[3], ay1[3], ax2[3], ay2[3], pA[3], dd[3];

        #pragma unroll
        for (int a = 0; a < 3; a++) {
            long base = (((long)b * 255 + a * 85) * 361) + idx;
            float x0 = __ldg(&out[base]);
            float y0 = __ldg(&out[base + 361]);
            zw[a] = __ldg(&out[base + 722]);
            zh[a] = __ldg(&out[base + 1083]);
            zo[a] = __ldg(&out[base + 1444]);
            sx[a] = 1.f / (1.f + __expf(-x0));
            sy[a] = 1.f / (1.f + __expf(-y0));
            float pw = __expf(zw[a]) * caw[a];
            float ph = __expf(zh[a]) * cah[a];
            float px = sx[a] + (float)i;
            float py = sy[a] + (float)j;
            ax1[a] = px - 0.5f * pw; ax2[a] = px + 0.5f * pw;
            ay1[a] = py - 0.5f * ph; ay2[a] = py + 0.5f * ph;
            pA[a] = pw * ph;
            dd[a] = -1e30f;
        }

        #pragma unroll 4
        for (int m = 0; m < MM; m++) {
            float4 c = ((const float4*)sT)[m * 2];
            float bA = sT[m * 8 + 4];
            #pragma unroll
            for (int a = 0; a < 3; a++) {
                float w = fminf(ax2[a], c.z) - fmaxf(ax1[a], c.x);
                float h = fminf(ay2[a], c.w) - fmaxf(ay1[a], c.y);
                float inter = fmaxf(w, 0.f) * fmaxf(h, 0.f);
                dd[a] = fmaxf(dd[a], __fmaf_rn(inter, 3.f, -(pA[a] + bA)));
            }
        }

        #pragma unroll
        for (int a = 0; a < 3; a++) {
            int flat = ((b * 3 + a) * FG + j) * FG + i;
            bool matched = (g_flag[flat] != 0);
            float so = 1.f / (1.f + __expf(-zo[a]));
            if (matched) {
                const float* P = &g_payload[flat][0];
                float4 p0 = *(const float4*)P;
                float txf = p0.x, tyf = p0.y, twt = p0.z, tht = p0.w;
                float sc = P[4];
                float w2 = sc * sc;
                float lpx = fmaxf(__logf(sx[a]), -100.f);
                float lqx = fmaxf(__logf(1.f - sx[a]), -100.f);
                float lpy = fmaxf(__logf(sy[a]), -100.f);
                float lqy = fmaxf(__logf(1.f - sy[a]), -100.f);
                a_xy += -w2 * (txf * lpx + (1.f - txf) * lqx)
                        - w2 * (tyf * lpy + (1.f - tyf) * lqy);
                float dw = zw[a] - twt, dh = zh[a] - tht;
                float whs = w2 * (dw * dw + dh * dh);
                a_wh += 0.5f * whs;
                a_obj += -fmaxf(__logf(so), -100.f);
                float ex = sx[a] - txf, ey = sy[a] - tyf, eo = so - 1.f;
                a_l2 += ex * ex + ey * ey + whs + eo * eo;
            } else if (dd[a] <= 0.f) {
                a_obj += -fmaxf(__logf(1.f - so), -100.f);
                a_l2 += so * so;
            }
        }
    }

    unsigned msk = 0xffffffffu;
    for (int off = 16; off > 0; off >>= 1) {
        a_xy  += __shfl_down_sync(msk, a_xy, off);
        a_wh  += __shfl_down_sync(msk, a_wh, off);
        a_obj += __shfl_down_sync(msk, a_obj, off);
        a_l2  += __shfl_down_sync(msk, a_l2, off);
    }
    if ((threadIdx.x & 31) == 0) {
        atomicAdd(&g_acc[1], (double)a_xy);
        atomicAdd(&g_acc[2], (double)a_wh);
        atomicAdd(&g_acc[3], (double)a_obj);
        atomicAdd(&g_acc[5], (double)a_l2);
    }
}

// One warp per matched cell: 80 class channels across lanes (3 rounds).
// Last block finalizes output and restores device-global state for replay.
__global__ void __launch_bounds__(256) k_cls(const float* __restrict__ out,
                                             float* __restrict__ o) {
    int gw = (blockIdx.x * 256 + threadIdx.x) >> 5;
    int lane = threadIdx.x & 31;
    int n = g_nmatch;
    float a_cls = 0.f, a_l2 = 0.f;

    if (gw < n) {
        int flat = g_mlist[gw];
        if (lane == 0) g_flag[flat] = 0;     // restore invariant for next replay
        int cls = (int)g_payload[flat][5];
        int idx = flat % 361;
        int a = (flat / 361) % 3;
        int b = flat / 1083;
        long cbase = ((long)(b * 255 + a * 85 + 5)) * 361 + idx;
        #pragma unroll
        for (int r = 0; r < 3; r++) {
            int cc = lane + r * 32;
            if (cc < NCc) {
                float z = __ldg(&out[cbase + (long)cc * 361]);
                float p = 1.f / (1.f + __expf(-z));
                float lp = fmaxf(__logf(p), -100.f);
                float lq = fmaxf(__logf(1.f - p), -100.f);
                float t = (cc == cls) ? 1.f : 0.f;
                a_cls += -(t * lp + (1.f - t) * lq);
                float e = p - t;
                a_l2 += e * e;
            }
        }
        unsigned msk = 0xffffffffu;
        for (int off = 16; off > 0; off >>= 1) {
            a_cls += __shfl_down_sync(msk, a_cls, off);
            a_l2  += __shfl_down_sync(msk, a_l2, off);
        }
        if (lane == 0) {
            atomicAdd(&g_acc[4], (double)a_cls);
            atomicAdd(&g_acc[5], (double)a_l2);
        }
    }

    __syncthreads();
    if (threadIdx.x == 0) {
        __threadfence();
        int d = atomicAdd(&g_done, 1);
        if (d == (int)gridDim.x - 1) {
            double xy = atomicAdd(&g_acc[1], 0.0);
            double wh = atomicAdd(&g_acc[2], 0.0);
            double ob = atomicAdd(&g_acc[3], 0.0);
            double cl = atomicAdd(&g_acc[4], 0.0);
            double l2 = atomicAdd(&g_acc[5], 0.0);
            o[0] = (float)(xy + wh + ob + cl);
            o[1] = (float)xy;
            o[2] = (float)wh;
            o[3] = (float)ob;
            o[4] = (float)cl;
            o[5] = (float)l2;
            g_done = 0;
            g_nmatch = 0;
        }
    }
}

extern "C" void kernel_launch(void* const* d_in, const int* in_sizes, int n_in,
                              void* d_out, int out_size) {
    const float* output = (const float*)d_in[0];
    const float* labels = (const float*)d_in[1];
    float* o = (float*)d_out;
    (void)in_sizes; (void)n_in; (void)out_size;

    k_scatter<<<BB, 64>>>(labels);
    dim3 g(3, BB);
    k_main<<<g, 128>>>(output);
    k_cls<<<(BB * MM + 7) / 8, 256>>>(output, o);
}

// round 3
// speedup vs baseline: 3.0658x; 1.6496x over previous
#include <cuda_runtime.h>

#define BB 128
#define MM 60
#define FG 19
#define NCc 80
#define NCELL (BB*3*FG*FG)   // 138624

__device__ double g_acc[6];
__device__ int    g_flag[NCELL];
__device__ float  g_payload[NCELL][8];
__device__ float  g_truth[BB][MM][8];
__device__ int    g_mlist[BB*MM];
__device__ int    g_nmatch;
__device__ int    g_done;

// anchors / 32 (exact in fp32)
__constant__ float c_aw[9] = {0.3125f, 0.5f,     1.03125f, 0.9375f, 1.9375f,
                              1.84375f, 3.625f,  4.875f,   11.65625f};
__constant__ float c_ah[9] = {0.40625f, 0.9375f, 0.71875f, 1.90625f, 1.40625f,
                              3.71875f, 2.8125f, 6.1875f,  10.1875f};

// Block per batch. Duplicate cells are resolved IN SHARED MEMORY (label m is
// dropped iff a later label m' maps to the same cell -> last-label-wins),
// then all surviving labels commit to global memory fully in parallel.
__global__ void __launch_bounds__(64) k_scatter(const float* __restrict__ labels) {
    int b = blockIdx.x;
    __shared__ float sL[MM * 5];
    __shared__ int   sFlat[MM];

    if (b == 0 && threadIdx.x < 6) g_acc[threadIdx.x] = 0.0;

    for (int t = threadIdx.x; t < MM * 5; t += 64)
        sL[t] = labels[b * (MM * 5) + t];
    __syncthreads();

    int m = threadIdx.x;
    float tx = 0.f, ty = 0.f, tw = 0.f, th = 0.f, ta = 0.f, l4 = 0.f;
    int bn = 0;
    if (m < MM) {
        float l0 = sL[m*5], l1 = sL[m*5+1], l2 = sL[m*5+2], l3 = sL[m*5+3];
        l4 = sL[m*5+4];
        bool valid = (l0 + l1 + l2 + l3 + l4) > 0.0f;
        tx = floorf(l0 * 0.03125f);
        ty = floorf(l1 * 0.03125f);
        tw = floorf((l2 - l0) * 0.03125f);
        th = floorf((l3 - l1) * 0.03125f);
        ta = tw * th;

        float* T = &g_truth[b][m][0];
        if (valid) {
            float hw = tw * 0.5f, hh = th * 0.5f;
            T[0] = tx - hw; T[1] = ty - hh; T[2] = tx + hw; T[3] = ty + hh; T[4] = ta;
        } else {
            T[0] = 3e18f; T[1] = 3e18f; T[2] = 3e18f; T[3] = 3e18f; T[4] = 0.f;
        }

        float best = -1.0f; int bi = 0;
        #pragma unroll
        for (int k = 0; k < 9; k++) {
            float mw = fminf(tw, c_aw[k]);
            float mh = fminf(th, c_ah[k]);
            float inter = (mw > 0.f && mh > 0.f) ? mw * mh : 0.f;
            float aiou = inter / (ta + c_aw[k] * c_ah[k] - inter);
            if (aiou > best) { best = aiou; bi = k; }
        }

        int flat = -1;
        if (valid && bi >= 6) {
            bn = bi - 6;
            int ti = (int)tx, tj = (int)ty;
            if (ti >= 0 && ti < FG && tj >= 0 && tj < FG)
                flat = ((b * 3 + bn) * FG + tj) * FG + ti;
        }
        sFlat[m] = flat;
    }
    __syncthreads();

    if (m < MM) {
        int flat = sFlat[m];
        if (flat >= 0) {
            // last-label-wins: drop if a later label hits the same cell
            bool keep = true;
            for (int m2 = m + 1; m2 < MM; m2++)
                if (sFlat[m2] == flat) { keep = false; break; }
            if (keep) {
                g_flag[flat] = 1;
                int p = atomicAdd(&g_nmatch, 1);
                g_mlist[p] = flat;
                float* P = &g_payload[flat][0];
                P[0] = tx - (float)((int)tx);
                P[1] = ty - (float)((int)ty);
                P[2] = logf(tw / c_aw[6 + bn] + 1e-16f);
                P[3] = logf(th / c_ah[6 + bn] + 1e-16f);
                P[4] = sqrtf(2.0f - ta / 361.0f);
                P[5] = l4;
            }
        }
    }
}

// One thread per (b, j, i); 3 anchors in registers; ignore-mask IoU pass +
// xy/wh/obj losses. Class loss handled in k_cls.
__global__ void __launch_bounds__(128) k_main(const float* __restrict__ out) {
    int b = blockIdx.y;
    __shared__ __align__(16) float sT[MM * 8];
    for (int t = threadIdx.x; t < MM * 2; t += blockDim.x)
        ((float4*)sT)[t] = ((const float4*)&g_truth[b][0][0])[t];
    __syncthreads();

    int idx = blockIdx.x * blockDim.x + threadIdx.x;
    float a_xy = 0.f, a_wh = 0.f, a_obj = 0.f, a_l2 = 0.f;

    if (idx < FG * FG) {
        int j = idx / FG, i = idx - j * FG;
        const float caw[3] = {3.625f, 4.875f, 11.65625f};
        const float cah[3] = {2.8125f, 6.1875f, 10.1875f};
        float sx[3], sy[3], zw[3], zh[3], zo[3];
        float ax1[3], ay1[3], ax2[3], ay2[3], pA[3], dd[3];

        #pragma unroll
        for (int a = 0; a < 3; a++) {
            long base = (((long)b * 255 + a * 85) * 361) + idx;
            float x0 = __ldg(&out[base]);
            float y0 = __ldg(&out[base + 361]);
            zw[a] = __ldg(&out[base + 722]);
            zh[a] = __ldg(&out[base + 1083]);
            zo[a] = __ldg(&out[base + 1444]);
            sx[a] = 1.f / (1.f + __expf(-x0));
            sy[a] = 1.f / (1.f + __expf(-y0));
            float pw = __expf(zw[a]) * caw[a];
            float ph = __expf(zh[a]) * cah[a];
            float px = sx[a] + (float)i;
            float py = sy[a] + (float)j;
            ax1[a] = px - 0.5f * pw; ax2[a] = px + 0.5f * pw;
            ay1[a] = py - 0.5f * ph; ay2[a] = py + 0.5f * ph;
            pA[a] = pw * ph;
            dd[a] = -1e30f;
        }

        #pragma unroll 4
        for (int m = 0; m < MM; m++) {
            float4 c = ((const float4*)sT)[m * 2];
            float bA = sT[m * 8 + 4];
            #pragma unroll
            for (int a = 0; a < 3; a++) {
                float w = fminf(ax2[a], c.z) - fmaxf(ax1[a], c.x);
                float h = fminf(ay2[a], c.w) - fmaxf(ay1[a], c.y);
                float inter = fmaxf(w, 0.f) * fmaxf(h, 0.f);
                dd[a] = fmaxf(dd[a], __fmaf_rn(inter, 3.f, -(pA[a] + bA)));
            }
        }

        #pragma unroll
        for (int a = 0; a < 3; a++) {
            int flat = ((b * 3 + a) * FG + j) * FG + i;
            bool matched = (g_flag[flat] != 0);
            float so = 1.f / (1.f + __expf(-zo[a]));
            if (matched) {
                const float* P = &g_payload[flat][0];
                float4 p0 = *(const float4*)P;
                float txf = p0.x, tyf = p0.y, twt = p0.z, tht = p0.w;
                float sc = P[4];
                float w2 = sc * sc;
                float lpx = fmaxf(__logf(sx[a]), -100.f);
                float lqx = fmaxf(__logf(1.f - sx[a]), -100.f);
                float lpy = fmaxf(__logf(sy[a]), -100.f);
                float lqy = fmaxf(__logf(1.f - sy[a]), -100.f);
                a_xy += -w2 * (txf * lpx + (1.f - txf) * lqx)
                        - w2 * (tyf * lpy + (1.f - tyf) * lqy);
                float dw = zw[a] - twt, dh = zh[a] - tht;
                float whs = w2 * (dw * dw + dh * dh);
                a_wh += 0.5f * whs;
                a_obj += -fmaxf(__logf(so), -100.f);
                float ex = sx[a] - txf, ey = sy[a] - tyf, eo = so - 1.f;
                a_l2 += ex * ex + ey * ey + whs + eo * eo;
            } else if (dd[a] <= 0.f) {
                a_obj += -fmaxf(__logf(1.f - so), -100.f);
                a_l2 += so * so;
            }
        }
    }

    unsigned msk = 0xffffffffu;
    for (int off = 16; off > 0; off >>= 1) {
        a_xy  += __shfl_down_sync(msk, a_xy, off);
        a_wh  += __shfl_down_sync(msk, a_wh, off);
        a_obj += __shfl_down_sync(msk, a_obj, off);
        a_l2  += __shfl_down_sync(msk, a_l2, off);
    }
    if ((threadIdx.x & 31) == 0) {
        atomicAdd(&g_acc[1], (double)a_xy);
        atomicAdd(&g_acc[2], (double)a_wh);
        atomicAdd(&g_acc[3], (double)a_obj);
        atomicAdd(&g_acc[5], (double)a_l2);
    }
}

// One warp per matched cell: 80 class channels across lanes (3 rounds).
// Last block finalizes output and restores device-global state for replay.
__global__ void __launch_bounds__(256) k_cls(const float* __restrict__ out,
                                             float* __restrict__ o) {
    int gw = (blockIdx.x * 256 + threadIdx.x) >> 5;
    int lane = threadIdx.x & 31;
    int n = g_nmatch;
    float a_cls = 0.f, a_l2 = 0.f;

    if (gw < n) {
        int flat = g_mlist[gw];
        if (lane == 0) g_flag[flat] = 0;     // restore invariant for next replay
        int cls = (int)g_payload[flat][5];
        int idx = flat % 361;
        int a = (flat / 361) % 3;
        int b = flat / 1083;
        long cbase = ((long)(b * 255 + a * 85 + 5)) * 361 + idx;
        #pragma unroll
        for (int r = 0; r < 3; r++) {
            int cc = lane + r * 32;
            if (cc < NCc) {
                float z = __ldg(&out[cbase + (long)cc * 361]);
                float p = 1.f / (1.f + __expf(-z));
                float lp = fmaxf(__logf(p), -100.f);
                float lq = fmaxf(__logf(1.f - p), -100.f);
                float t = (cc == cls) ? 1.f : 0.f;
                a_cls += -(t * lp + (1.f - t) * lq);
                float e = p - t;
                a_l2 += e * e;
            }
        }
        unsigned msk = 0xffffffffu;
        for (int off = 16; off > 0; off >>= 1) {
            a_cls += __shfl_down_sync(msk, a_cls, off);
            a_l2  += __shfl_down_sync(msk, a_l2, off);
        }
        if (lane == 0) {
            atomicAdd(&g_acc[4], (double)a_cls);
            atomicAdd(&g_acc[5], (double)a_l2);
        }
    }

    __syncthreads();
    if (threadIdx.x == 0) {
        __threadfence();
        int d = atomicAdd(&g_done, 1);
        if (d == (int)gridDim.x - 1) {
            double xy = atomicAdd(&g_acc[1], 0.0);
            double wh = atomicAdd(&g_acc[2], 0.0);
            double ob = atomicAdd(&g_acc[3], 0.0);
            double cl = atomicAdd(&g_acc[4], 0.0);
            double l2 = atomicAdd(&g_acc[5], 0.0);
            o[0] = (float)(xy + wh + ob + cl);
            o[1] = (float)xy;
            o[2] = (float)wh;
            o[3] = (float)ob;
            o[4] = (float)cl;
            o[5] = (float)l2;
            g_done = 0;
            g_nmatch = 0;
        }
    }
}

extern "C" void kernel_launch(void* const* d_in, const int* in_sizes, int n_in,
                              void* d_out, int out_size) {
    const float* output = (const float*)d_in[0];
    const float* labels = (const float*)d_in[1];
    float* o = (float*)d_out;
    (void)in_sizes; (void)n_in; (void)out_size;

    k_scatter<<<BB, 64>>>(labels);
    dim3 g(3, BB);
    k_main<<<g, 128>>>(output);
    k_cls<<<(BB * MM + 7) / 8, 256>>>(output, o);
}

// round 4
// speedup vs baseline: 5.8208x; 1.8986x over previous
#include <cuda_runtime.h>

#define BB 128
#define MM 60
#define FG 19
#define NCc 80
#define CELLS (FG*FG)      // 361
#define LCELL (3*CELLS)    // 1083

__device__ double g_acc[6];   // zero-initialized at load; restored each launch
__device__ int    g_done;

// anchors / 32 (exact in fp32)
__constant__ float c_aw[9] = {0.3125f, 0.5f,     1.03125f, 0.9375f, 1.9375f,
                              1.84375f, 3.625f,  4.875f,   11.65625f};
__constant__ float c_ah[9] = {0.40625f, 0.9375f, 0.71875f, 1.90625f, 1.40625f,
                              3.71875f, 2.8125f, 6.1875f,  10.1875f};

__global__ void __launch_bounds__(384)
k_fused(const float* __restrict__ out, const float* __restrict__ labels,
        float* __restrict__ o) {
    int b = blockIdx.x;
    int tid = threadIdx.x;

    __shared__ float  sL[MM * 5];
    __shared__ float4 sTc[MM];        // truth corners x1,y1,x2,y2
    __shared__ float  sTa[MM];        // truth area
    __shared__ float  sPay[MM][6];    // txf,tyf,twt,tht,sc,cls
    __shared__ int    sFlat[MM];
    __shared__ short  sCell[LCELL];   // matched payload index per local cell, -1 none
    __shared__ short  sMm[MM];        // matched label indices
    __shared__ short  sMloc[MM];      // matched local cell (a*361+idx)
    __shared__ int    sN;
    __shared__ float  sRed[12][5];

    if (tid == 0) sN = 0;
    for (int t = tid; t < MM * 5; t += 384) sL[t] = labels[b * (MM * 5) + t];
    for (int t = tid; t < LCELL; t += 384) sCell[t] = -1;
    __syncthreads();

    // ---- phase 2: per-label truth boxes + anchor matching (threads 0..59) ----
    if (tid < MM) {
        int m = tid;
        float l0 = sL[m*5], l1 = sL[m*5+1], l2 = sL[m*5+2], l3 = sL[m*5+3], l4 = sL[m*5+4];
        bool valid = (l0 + l1 + l2 + l3 + l4) > 0.0f;
        float tx = floorf(l0 * 0.03125f);
        float ty = floorf(l1 * 0.03125f);
        float tw = floorf((l2 - l0) * 0.03125f);
        float th = floorf((l3 - l1) * 0.03125f);
        float ta = tw * th;

        if (valid) {
            float hw = tw * 0.5f, hh = th * 0.5f;
            sTc[m] = make_float4(tx - hw, ty - hh, tx + hw, ty + hh);
            sTa[m] = ta;
        } else {
            sTc[m] = make_float4(3e18f, 3e18f, 3e18f, 3e18f);
            sTa[m] = 0.f;
        }

        float best = -1.0f; int bi = 0;
        #pragma unroll
        for (int k = 0; k < 9; k++) {
            float mw = fminf(tw, c_aw[k]);
            float mh = fminf(th, c_ah[k]);
            float inter = (mw > 0.f && mh > 0.f) ? mw * mh : 0.f;
            float aiou = inter / (ta + c_aw[k] * c_ah[k] - inter);
            if (aiou > best) { best = aiou; bi = k; }
        }

        int flat = -1;
        if (valid && bi >= 6) {
            int bn = bi - 6;
            int ti = (int)tx, tj = (int)ty;
            if (ti >= 0 && ti < FG && tj >= 0 && tj < FG) {
                flat = (bn * FG + tj) * FG + ti;
                sPay[m][0] = tx - (float)((int)tx);
                sPay[m][1] = ty - (float)((int)ty);
                sPay[m][2] = logf(tw / c_aw[6 + bn] + 1e-16f);
                sPay[m][3] = logf(th / c_ah[6 + bn] + 1e-16f);
                sPay[m][4] = sqrtf(2.0f - ta / 361.0f);
                sPay[m][5] = l4;
            }
        }
        sFlat[m] = flat;
    }
    __syncthreads();

    // ---- dedup (last-label-wins) + build matched list, all in smem ----
    if (tid < MM) {
        int flat = sFlat[tid];
        if (flat >= 0) {
            bool keep = true;
            for (int m2 = tid + 1; m2 < MM; m2++)
                if (sFlat[m2] == flat) { keep = false; break; }
            if (keep) {
                sCell[flat] = (short)tid;
                int p = atomicAdd(&sN, 1);
                sMm[p] = (short)tid;
                sMloc[p] = (short)flat;
            }
        }
    }
    __syncthreads();

    // ---- phase 3: per-cell IoU ignore-mask + xy/wh/obj losses ----
    float a_xy = 0.f, a_wh = 0.f, a_obj = 0.f, a_cls = 0.f, a_l2 = 0.f;

    if (tid < CELLS) {
        int idx = tid;
        int j = idx / FG, i = idx - j * FG;
        const float caw[3] = {3.625f, 4.875f, 11.65625f};
        const float cah[3] = {2.8125f, 6.1875f, 10.1875f};
        float sx[3], sy[3], zw[3], zh[3], zo[3];
        float ax1[3], ay1[3], ax2[3], ay2[3], pA[3], dd[3];

        #pragma unroll
        for (int a = 0; a < 3; a++) {
            size_t base = ((size_t)(b * 255 + a * 85)) * CELLS + idx;
            float x0 = __ldg(&out[base]);
            float y0 = __ldg(&out[base + CELLS]);
            zw[a] = __ldg(&out[base + 2 * CELLS]);
            zh[a] = __ldg(&out[base + 3 * CELLS]);
            zo[a] = __ldg(&out[base + 4 * CELLS]);
            sx[a] = 1.f / (1.f + __expf(-x0));
            sy[a] = 1.f / (1.f + __expf(-y0));
            float pw = __expf(zw[a]) * caw[a];
            float ph = __expf(zh[a]) * cah[a];
            float px = sx[a] + (float)i;
            float py = sy[a] + (float)j;
            ax1[a] = px - 0.5f * pw; ax2[a] = px + 0.5f * pw;
            ay1[a] = py - 0.5f * ph; ay2[a] = py + 0.5f * ph;
            pA[a] = pw * ph;
            dd[a] = -1e30f;
        }

        #pragma unroll 4
        for (int m = 0; m < MM; m++) {
            float4 c = sTc[m];
            float bA = sTa[m];
            #pragma unroll
            for (int a = 0; a < 3; a++) {
                float w = fminf(ax2[a], c.z) - fmaxf(ax1[a], c.x);
                float h = fminf(ay2[a], c.w) - fmaxf(ay1[a], c.y);
                float inter = fmaxf(w, 0.f) * fmaxf(h, 0.f);
                dd[a] = fmaxf(dd[a], __fmaf_rn(inter, 3.f, -(pA[a] + bA)));
            }
        }

        #pragma unroll
        for (int a = 0; a < 3; a++) {
            int pm = sCell[a * CELLS + idx];
            float so = 1.f / (1.f + __expf(-zo[a]));
            if (pm >= 0) {
                const float* P = &sPay[pm][0];
                float txf = P[0], tyf = P[1], twt = P[2], tht = P[3], sc = P[4];
                float w2 = sc * sc;
                float lpx = fmaxf(__logf(sx[a]), -100.f);
                float lqx = fmaxf(__logf(1.f - sx[a]), -100.f);
                float lpy = fmaxf(__logf(sy[a]), -100.f);
                float lqy = fmaxf(__logf(1.f - sy[a]), -100.f);
                a_xy += -w2 * (txf * lpx + (1.f - txf) * lqx)
                        - w2 * (tyf * lpy + (1.f - tyf) * lqy);
                float dw = zw[a] - twt, dh = zh[a] - tht;
                float whs = w2 * (dw * dw + dh * dh);
                a_wh += 0.5f * whs;
                a_obj += -fmaxf(__logf(so), -100.f);
                float ex = sx[a] - txf, ey = sy[a] - tyf, eo = so - 1.f;
                a_l2 += ex * ex + ey * ey + whs + eo * eo;
            } else if (dd[a] <= 0.f) {
                a_obj += -fmaxf(__logf(1.f - so), -100.f);
                a_l2 += so * so;
            }
        }
    }

    // ---- phase 4: class loss, one warp per matched cell ----
    int wid = tid >> 5, lane = tid & 31;
    int n = sN;
    for (int w = wid; w < n; w += 12) {
        int m = sMm[w];
        int loc = sMloc[w];
        int cls = (int)sPay[m][5];
        int a = loc / CELLS;
        int idx = loc - a * CELLS;
        size_t cbase = ((size_t)(b * 255 + a * 85 + 5)) * CELLS + idx;
        #pragma unroll
        for (int r = 0; r < 3; r++) {
            int cc = lane + r * 32;
            if (cc < NCc) {
                float z = __ldg(&out[cbase + (size_t)cc * CELLS]);
                float p = 1.f / (1.f + __expf(-z));
                float lp = fmaxf(__logf(p), -100.f);
                float lq = fmaxf(__logf(1.f - p), -100.f);
                float t = (cc == cls) ? 1.f : 0.f;
                a_cls += -(t * lp + (1.f - t) * lq);
                float e = p - t;
                a_l2 += e * e;
            }
        }
    }

    // ---- reduce: warp shuffle -> smem -> thread 0 -> double atomics ----
    unsigned msk = 0xffffffffu;
    for (int off = 16; off > 0; off >>= 1) {
        a_xy  += __shfl_down_sync(msk, a_xy, off);
        a_wh  += __shfl_down_sync(msk, a_wh, off);
        a_obj += __shfl_down_sync(msk, a_obj, off);
        a_cls += __shfl_down_sync(msk, a_cls, off);
        a_l2  += __shfl_down_sync(msk, a_l2, off);
    }
    if (lane == 0) {
        sRed[wid][0] = a_xy; sRed[wid][1] = a_wh; sRed[wid][2] = a_obj;
        sRed[wid][3] = a_cls; sRed[wid][4] = a_l2;
    }
    __syncthreads();
    if (tid == 0) {
        float r0 = 0.f, r1 = 0.f, r2 = 0.f, r3 = 0.f, r4 = 0.f;
        #pragma unroll
        for (int w = 0; w < 12; w++) {
            r0 += sRed[w][0]; r1 += sRed[w][1]; r2 += sRed[w][2];
            r3 += sRed[w][3]; r4 += sRed[w][4];
        }
        atomicAdd(&g_acc[1], (double)r0);
        atomicAdd(&g_acc[2], (double)r1);
        atomicAdd(&g_acc[3], (double)r2);
        atomicAdd(&g_acc[4], (double)r3);
        atomicAdd(&g_acc[5], (double)r4);
        __threadfence();
        int d = atomicAdd(&g_done, 1);
        if (d == BB - 1) {
            double xy = atomicAdd(&g_acc[1], 0.0);
            double wh = atomicAdd(&g_acc[2], 0.0);
            double ob = atomicAdd(&g_acc[3], 0.0);
            double cl = atomicAdd(&g_acc[4], 0.0);
            double l2 = atomicAdd(&g_acc[5], 0.0);
            o[0] = (float)(xy + wh + ob + cl);
            o[1] = (float)xy;
            o[2] = (float)wh;
            o[3] = (float)ob;
            o[4] = (float)cl;
            o[5] = (float)l2;
            // restore state for next graph replay
            g_acc[1] = 0.0; g_acc[2] = 0.0; g_acc[3] = 0.0;
            g_acc[4] = 0.0; g_acc[5] = 0.0;
            g_done = 0;
        }
    }
}

extern "C" void kernel_launch(void* const* d_in, const int* in_sizes, int n_in,
                              void* d_out, int out_size) {
    const float* output = (const float*)d_in[0];
    const float* labels = (const float*)d_in[1];
    float* o = (float*)d_out;
    (void)in_sizes; (void)n_in; (void)out_size;

    k_fused<<<BB, 384>>>(output, labels, o);
}

// round 5
// speedup vs baseline: 6.8931x; 1.1842x over previous
#include <cuda_runtime.h>

#define BB 128
#define MM 60
#define FG 19
#define NCc 80
#define CELLS (FG*FG)      // 361
#define NBLK (BB*3)        // 384

__device__ double g_acc[6];   // zero-initialized at load; restored each launch
__device__ int    g_done;

// anchors / 32 (exact in fp32)
__constant__ float c_aw[9] = {0.3125f, 0.5f,     1.03125f, 0.9375f, 1.9375f,
                              1.84375f, 3.625f,  4.875f,   11.65625f};
__constant__ float c_ah[9] = {0.40625f, 0.9375f, 0.71875f, 1.90625f, 1.40625f,
                              3.71875f, 2.8125f, 6.1875f,  10.1875f};

// One block per (batch, anchor). 384 threads.
__global__ void __launch_bounds__(384)
k_fused(const float* __restrict__ out, const float* __restrict__ labels,
        float* __restrict__ o) {
    int b = blockIdx.x;
    int anc = blockIdx.y;          // this block's anchor (0..2)
    int tid = threadIdx.x;

    __shared__ float  sL[MM * 5];
    __shared__ float4 sTc[MM];        // truth corners x1,y1,x2,y2
    __shared__ float  sTa[MM];        // truth area
    __shared__ float  sPay[MM][6];    // txf,tyf,twt,tht,sc,cls (this anchor only)
    __shared__ int    sFlat[MM];      // cell idx if matched to THIS anchor
    __shared__ short  sCell[CELLS];   // payload index per cell, -1 none
    __shared__ short  sMm[MM];        // matched label indices
    __shared__ short  sMloc[MM];      // matched cell idx
    __shared__ int    sN;
    __shared__ float  sRed[12][5];

    if (tid == 0) sN = 0;
    for (int t = tid; t < MM * 5; t += 384) sL[t] = labels[b * (MM * 5) + t];
    for (int t = tid; t < CELLS; t += 384) sCell[t] = -1;
    __syncthreads();

    // ---- per-label truth boxes + anchor matching (threads 0..59) ----
    if (tid < MM) {
        int m = tid;
        float l0 = sL[m*5], l1 = sL[m*5+1], l2 = sL[m*5+2], l3 = sL[m*5+3], l4 = sL[m*5+4];
        bool valid = (l0 + l1 + l2 + l3 + l4) > 0.0f;
        float tx = floorf(l0 * 0.03125f);
        float ty = floorf(l1 * 0.03125f);
        float tw = floorf((l2 - l0) * 0.03125f);
        float th = floorf((l3 - l1) * 0.03125f);
        float ta = tw * th;

        if (valid) {
            float hw = tw * 0.5f, hh = th * 0.5f;
            sTc[m] = make_float4(tx - hw, ty - hh, tx + hw, ty + hh);
            sTa[m] = ta;
        } else {
            sTc[m] = make_float4(3e18f, 3e18f, 3e18f, 3e18f);
            sTa[m] = 0.f;
        }

        float best = -1.0f; int bi = 0;
        #pragma unroll
        for (int k = 0; k < 9; k++) {
            float mw = fminf(tw, c_aw[k]);
            float mh = fminf(th, c_ah[k]);
            float inter = (mw > 0.f && mh > 0.f) ? mw * mh : 0.f;
            float aiou = inter / (ta + c_aw[k] * c_ah[k] - inter);
            if (aiou > best) { best = aiou; bi = k; }
        }

        int flat = -1;
        if (valid && bi == 6 + anc) {        // matched to THIS block's anchor
            int ti = (int)tx, tj = (int)ty;
            if (ti >= 0 && ti < FG && tj >= 0 && tj < FG) {
                flat = tj * FG + ti;
                sPay[m][0] = tx - (float)((int)tx);
                sPay[m][1] = ty - (float)((int)ty);
                sPay[m][2] = logf(tw / c_aw[6 + anc] + 1e-16f);
                sPay[m][3] = logf(th / c_ah[6 + anc] + 1e-16f);
                sPay[m][4] = sqrtf(2.0f - ta / 361.0f);
                sPay[m][5] = l4;
            }
        }
        sFlat[m] = flat;
    }
    __syncthreads();

    // ---- dedup (last-label-wins within this anchor) + matched list ----
    if (tid < MM) {
        int flat = sFlat[tid];
        if (flat >= 0) {
            bool keep = true;
            for (int m2 = tid + 1; m2 < MM; m2++)
                if (sFlat[m2] == flat) { keep = false; break; }
            if (keep) {
                sCell[flat] = (short)tid;
                int p = atomicAdd(&sN, 1);
                sMm[p] = (short)tid;
                sMloc[p] = (short)flat;
            }
        }
    }
    __syncthreads();

    // ---- per-cell IoU ignore-mask + xy/wh/obj losses (this anchor) ----
    float a_xy = 0.f, a_wh = 0.f, a_obj = 0.f, a_cls = 0.f, a_l2 = 0.f;

    if (tid < CELLS) {
        int idx = tid;
        int j = idx / FG, i = idx - j * FG;
        float caw = c_aw[6 + anc], cah = c_ah[6 + anc];

        size_t base = ((size_t)(b * 255 + anc * 85)) * CELLS + idx;
        float x0 = __ldg(&out[base]);
        float y0 = __ldg(&out[base + CELLS]);
        float zw = __ldg(&out[base + 2 * CELLS]);
        float zh = __ldg(&out[base + 3 * CELLS]);
        float zo = __ldg(&out[base + 4 * CELLS]);
        float sx = 1.f / (1.f + __expf(-x0));
        float sy = 1.f / (1.f + __expf(-y0));
        float pw = __expf(zw) * caw;
        float ph = __expf(zh) * cah;
        float px = sx + (float)i;
        float py = sy + (float)j;
        float ax1 = px - 0.5f * pw, ax2 = px + 0.5f * pw;
        float ay1 = py - 0.5f * ph, ay2 = py + 0.5f * ph;
        float pA = pw * ph;

        // 4 independent max-chains for ILP (MM=60 divisible by 4)
        float d0 = -1e30f, d1 = -1e30f, d2 = -1e30f, d3 = -1e30f;
        #pragma unroll 4
        for (int m = 0; m < MM; m += 4) {
            {
                float4 c = sTc[m];   float bA = sTa[m];
                float w = fminf(ax2, c.z) - fmaxf(ax1, c.x);
                float h = fminf(ay2, c.w) - fmaxf(ay1, c.y);
                float inter = fmaxf(w, 0.f) * fmaxf(h, 0.f);
                d0 = fmaxf(d0, __fmaf_rn(inter, 3.f, -(pA + bA)));
            }
            {
                float4 c = sTc[m+1]; float bA = sTa[m+1];
                float w = fminf(ax2, c.z) - fmaxf(ax1, c.x);
                float h = fminf(ay2, c.w) - fmaxf(ay1, c.y);
                float inter = fmaxf(w, 0.f) * fmaxf(h, 0.f);
                d1 = fmaxf(d1, __fmaf_rn(inter, 3.f, -(pA + bA)));
            }
            {
                float4 c = sTc[m+2]; float bA = sTa[m+2];
                float w = fminf(ax2, c.z) - fmaxf(ax1, c.x);
                float h = fminf(ay2, c.w) - fmaxf(ay1, c.y);
                float inter = fmaxf(w, 0.f) * fmaxf(h, 0.f);
                d2 = fmaxf(d2, __fmaf_rn(inter, 3.f, -(pA + bA)));
            }
            {
                float4 c = sTc[m+3]; float bA = sTa[m+3];
                float w = fminf(ax2, c.z) - fmaxf(ax1, c.x);
                float h = fminf(ay2, c.w) - fmaxf(ay1, c.y);
                float inter = fmaxf(w, 0.f) * fmaxf(h, 0.f);
                d3 = fmaxf(d3, __fmaf_rn(inter, 3.f, -(pA + bA)));
            }
        }
        float dd = fmaxf(fmaxf(d0, d1), fmaxf(d2, d3));

        int pm = sCell[idx];
        float so = 1.f / (1.f + __expf(-zo));
        if (pm >= 0) {
            const float* P = &sPay[pm][0];
            float txf = P[0], tyf = P[1], twt = P[2], tht = P[3], sc = P[4];
            float w2 = sc * sc;
            float lpx = fmaxf(__logf(sx), -100.f);
            float lqx = fmaxf(__logf(1.f - sx), -100.f);
            float lpy = fmaxf(__logf(sy), -100.f);
            float lqy = fmaxf(__logf(1.f - sy), -100.f);
            a_xy += -w2 * (txf * lpx + (1.f - txf) * lqx)
                    - w2 * (tyf * lpy + (1.f - tyf) * lqy);
            float dw = zw - twt, dh = zh - tht;
            float whs = w2 * (dw * dw + dh * dh);
            a_wh += 0.5f * whs;
            a_obj += -fmaxf(__logf(so), -100.f);
            float ex = sx - txf, ey = sy - tyf, eo = so - 1.f;
            a_l2 += ex * ex + ey * ey + whs + eo * eo;
        } else if (dd <= 0.f) {
            a_obj += -fmaxf(__logf(1.f - so), -100.f);
            a_l2 += so * so;
        }
    }

    // ---- class loss: one warp per matched cell of this anchor ----
    int wid = tid >> 5, lane = tid & 31;
    int n = sN;
    for (int w = wid; w < n; w += 12) {
        int m = sMm[w];
        int idx = sMloc[w];
        int cls = (int)sPay[m][5];
        size_t cbase = ((size_t)(b * 255 + anc * 85 + 5)) * CELLS + idx;
        #pragma unroll
        for (int r = 0; r < 3; r++) {
            int cc = lane + r * 32;
            if (cc < NCc) {
                float z = __ldg(&out[cbase + (size_t)cc * CELLS]);
                float p = 1.f / (1.f + __expf(-z));
                float lp = fmaxf(__logf(p), -100.f);
                float lq = fmaxf(__logf(1.f - p), -100.f);
                float t = (cc == cls) ? 1.f : 0.f;
                a_cls += -(t * lp + (1.f - t) * lq);
                float e = p - t;
                a_l2 += e * e;
            }
        }
    }

    // ---- reduce: warp shuffle -> smem -> thread 0 -> double atomics ----
    unsigned msk = 0xffffffffu;
    for (int off = 16; off > 0; off >>= 1) {
        a_xy  += __shfl_down_sync(msk, a_xy, off);
        a_wh  += __shfl_down_sync(msk, a_wh, off);
        a_obj += __shfl_down_sync(msk, a_obj, off);
        a_cls += __shfl_down_sync(msk, a_cls, off);
        a_l2  += __shfl_down_sync(msk, a_l2, off);
    }
    if (lane == 0) {
        sRed[wid][0] = a_xy; sRed[wid][1] = a_wh; sRed[wid][2] = a_obj;
        sRed[wid][3] = a_cls; sRed[wid][4] = a_l2;
    }
    __syncthreads();
    if (tid == 0) {
        float r0 = 0.f, r1 = 0.f, r2 = 0.f, r3 = 0.f, r4 = 0.f;
        #pragma unroll
        for (int w = 0; w < 12; w++) {
            r0 += sRed[w][0]; r1 += sRed[w][1]; r2 += sRed[w][2];
            r3 += sRed[w][3]; r4 += sRed[w][4];
        }
        atomicAdd(&g_acc[1], (double)r0);
        atomicAdd(&g_acc[2], (double)r1);
        atomicAdd(&g_acc[3], (double)r2);
        atomicAdd(&g_acc[4], (double)r3);
        atomicAdd(&g_acc[5], (double)r4);
        __threadfence();
        int d = atomicAdd(&g_done, 1);
        if (d == NBLK - 1) {
            double xy = atomicAdd(&g_acc[1], 0.0);
            double wh = atomicAdd(&g_acc[2], 0.0);
            double ob = atomicAdd(&g_acc[3], 0.0);
            double cl = atomicAdd(&g_acc[4], 0.0);
            double l2 = atomicAdd(&g_acc[5], 0.0);
            o[0] = (float)(xy + wh + ob + cl);
            o[1] = (float)xy;
            o[2] = (float)wh;
            o[3] = (float)ob;
            o[4] = (float)cl;
            o[5] = (float)l2;
            // restore state for next graph replay
            g_acc[1] = 0.0; g_acc[2] = 0.0; g_acc[3] = 0.0;
            g_acc[4] = 0.0; g_acc[5] = 0.0;
            g_done = 0;
        }
    }
}

extern "C" void kernel_launch(void* const* d_in, const int* in_sizes, int n_in,
                              void* d_out, int out_size) {
    const float* output = (const float*)d_in[0];
    const float* labels = (const float*)d_in[1];
    float* o = (float*)d_out;
    (void)in_sizes; (void)n_in; (void)out_size;

    dim3 grid(BB, 3);
    k_fused<<<grid, 384>>>(output, labels, o);
}

// round 6
// speedup vs baseline: 7.8190x; 1.1343x over previous
#include <cuda_runtime.h>

#define BB 128
#define MM 60
#define FG 19
#define NCc 80
#define CELLS (FG*FG)      // 361
#define NBLK (BB*3)        // 384

__device__ double g_acc[6];   // zero-initialized at load; restored each launch
__device__ int    g_done;

// anchors / 32 (exact in fp32)
__constant__ float c_aw[9] = {0.3125f, 0.5f,     1.03125f, 0.9375f, 1.9375f,
                              1.84375f, 3.625f,  4.875f,   11.65625f};
__constant__ float c_ah[9] = {0.40625f, 0.9375f, 0.71875f, 1.90625f, 1.40625f,
                              3.71875f, 2.8125f, 6.1875f,  10.1875f};

// One block per (batch, anchor). 384 threads, >=4 blocks/SM.
__global__ void __launch_bounds__(384, 4)
k_fused(const float* __restrict__ out, const float* __restrict__ labels,
        float* __restrict__ o) {
    int b = blockIdx.x;
    int anc = blockIdx.y;
    int tid = threadIdx.x;

    __shared__ float  sL[MM * 5];
    __shared__ float4 sTc[MM];        // truth corners x1,y1,x2,y2
    __shared__ float  sTa[MM];        // truth area
    __shared__ float  sPay[MM][6];    // txf,tyf,twt,tht,sc,cls
    __shared__ int    sCellI[CELLS];  // winning label per cell via atomicMax, -1 none
    __shared__ short  sMm[MM];        // matched label indices
    __shared__ short  sMloc[MM];      // matched cell idx
    __shared__ int    sN;
    __shared__ float  sRed[12][5];

    // ---- prefetch this thread's 5 channel values (latency overlaps scatter) ----
    float x0 = 0.f, y0 = 0.f, zw = 0.f, zh = 0.f, zo = 0.f;
    if (tid < CELLS) {
        size_t base = ((size_t)(b * 255 + anc * 85)) * CELLS + tid;
        x0 = __ldg(&out[base]);
        y0 = __ldg(&out[base + CELLS]);
        zw = __ldg(&out[base + 2 * CELLS]);
        zh = __ldg(&out[base + 3 * CELLS]);
        zo = __ldg(&out[base + 4 * CELLS]);
    }

    if (tid == 0) sN = 0;
    for (int t = tid; t < MM * 5; t += 384) sL[t] = labels[b * (MM * 5) + t];
    for (int t = tid; t < CELLS; t += 384) sCellI[t] = -1;
    __syncthreads();

    // ---- per-label truth boxes + anchor matching + atomicMax claim ----
    int myflat = -1;
    if (tid < MM) {
        int m = tid;
        float l0 = sL[m*5], l1 = sL[m*5+1], l2 = sL[m*5+2], l3 = sL[m*5+3], l4 = sL[m*5+4];
        bool valid = (l0 + l1 + l2 + l3 + l4) > 0.0f;
        float tx = floorf(l0 * 0.03125f);
        float ty = floorf(l1 * 0.03125f);
        float tw = floorf((l2 - l0) * 0.03125f);
        float th = floorf((l3 - l1) * 0.03125f);
        float ta = tw * th;

        if (valid) {
            float hw = tw * 0.5f, hh = th * 0.5f;
            sTc[m] = make_float4(tx - hw, ty - hh, tx + hw, ty + hh);
            sTa[m] = ta;
        } else {
            sTc[m] = make_float4(3e18f, 3e18f, 3e18f, 3e18f);
            sTa[m] = 0.f;
        }

        float best = -1.0f; int bi = 0;
        #pragma unroll
        for (int k = 0; k < 9; k++) {
            float mw = fminf(tw, c_aw[k]);
            float mh = fminf(th, c_ah[k]);
            float inter = (mw > 0.f && mh > 0.f) ? mw * mh : 0.f;
            float aiou = inter / (ta + c_aw[k] * c_ah[k] - inter);
            if (aiou > best) { best = aiou; bi = k; }
        }

        if (valid && bi == 6 + anc) {
            int ti = (int)tx, tj = (int)ty;
            if (ti >= 0 && ti < FG && tj >= 0 && tj < FG) {
                myflat = tj * FG + ti;
                sPay[m][0] = tx - (float)((int)tx);
                sPay[m][1] = ty - (float)((int)ty);
                sPay[m][2] = logf(tw / c_aw[6 + anc] + 1e-16f);
                sPay[m][3] = logf(th / c_ah[6 + anc] + 1e-16f);
                sPay[m][4] = sqrtf(2.0f - ta / 361.0f);
                sPay[m][5] = l4;
                atomicMax(&sCellI[myflat], m);   // last-label-wins == max m
            }
        }
    }
    __syncthreads();

    // winners append to the matched list (consumed only by the class phase,
    // which is separated from here by another __syncthreads)
    if (tid < MM && myflat >= 0 && sCellI[myflat] == tid) {
        int p = atomicAdd(&sN, 1);
        sMm[p] = (short)tid;
        sMloc[p] = (short)myflat;
    }

    // ---- per-cell IoU ignore-mask + xy/wh/obj losses ----
    float a_xy = 0.f, a_wh = 0.f, a_obj = 0.f, a_cls = 0.f, a_l2 = 0.f;

    if (tid < CELLS) {
        int idx = tid;
        int j = idx / FG, i = idx - j * FG;
        float caw = c_aw[6 + anc], cah = c_ah[6 + anc];

        float sx = 1.f / (1.f + __expf(-x0));
        float sy = 1.f / (1.f + __expf(-y0));
        float pw = __expf(zw) * caw;
        float ph = __expf(zh) * cah;
        float px = sx + (float)i;
        float py = sy + (float)j;
        float ax1 = px - 0.5f * pw, ax2 = px + 0.5f * pw;
        float ay1 = py - 0.5f * ph, ay2 = py + 0.5f * ph;
        float pA = pw * ph;

        float d0 = -1e30f, d1 = -1e30f, d2 = -1e30f, d3 = -1e30f;
        #pragma unroll 4
        for (int m = 0; m < MM; m += 4) {
            {
                float4 c = sTc[m];   float bA = sTa[m];
                float w = fminf(ax2, c.z) - fmaxf(ax1, c.x);
                float h = fminf(ay2, c.w) - fmaxf(ay1, c.y);
                float inter = fmaxf(w, 0.f) * fmaxf(h, 0.f);
                d0 = fmaxf(d0, __fmaf_rn(inter, 3.f, -(pA + bA)));
            }
            {
                float4 c = sTc[m+1]; float bA = sTa[m+1];
                float w = fminf(ax2, c.z) - fmaxf(ax1, c.x);
                float h = fminf(ay2, c.w) - fmaxf(ay1, c.y);
                float inter = fmaxf(w, 0.f) * fmaxf(h, 0.f);
                d1 = fmaxf(d1, __fmaf_rn(inter, 3.f, -(pA + bA)));
            }
            {
                float4 c = sTc[m+2]; float bA = sTa[m+2];
                float w = fminf(ax2, c.z) - fmaxf(ax1, c.x);
                float h = fminf(ay2, c.w) - fmaxf(ay1, c.y);
                float inter = fmaxf(w, 0.f) * fmaxf(h, 0.f);
                d2 = fmaxf(d2, __fmaf_rn(inter, 3.f, -(pA + bA)));
            }
            {
                float4 c = sTc[m+3]; float bA = sTa[m+3];
                float w = fminf(ax2, c.z) - fmaxf(ax1, c.x);
                float h = fminf(ay2, c.w) - fmaxf(ay1, c.y);
                float inter = fmaxf(w, 0.f) * fmaxf(h, 0.f);
                d3 = fmaxf(d3, __fmaf_rn(inter, 3.f, -(pA + bA)));
            }
        }
        float dd = fmaxf(fmaxf(d0, d1), fmaxf(d2, d3));

        int pm = sCellI[idx];
        float so = 1.f / (1.f + __expf(-zo));
        if (pm >= 0) {
            const float* P = &sPay[pm][0];
            float txf = P[0], tyf = P[1], twt = P[2], tht = P[3], sc = P[4];
            float w2 = sc * sc;
            float lpx = fmaxf(__logf(sx), -100.f);
            float lqx = fmaxf(__logf(1.f - sx), -100.f);
            float lpy = fmaxf(__logf(sy), -100.f);
            float lqy = fmaxf(__logf(1.f - sy), -100.f);
            a_xy += -w2 * (txf * lpx + (1.f - txf) * lqx)
                    - w2 * (tyf * lpy + (1.f - tyf) * lqy);
            float dw = zw - twt, dh = zh - tht;
            float whs = w2 * (dw * dw + dh * dh);
            a_wh += 0.5f * whs;
            a_obj += -fmaxf(__logf(so), -100.f);
            float ex = sx - txf, ey = sy - tyf, eo = so - 1.f;
            a_l2 += ex * ex + ey * ey + whs + eo * eo;
        } else if (dd <= 0.f) {
            a_obj += -fmaxf(__logf(1.f - so), -100.f);
            a_l2 += so * so;
        }
    }
    __syncthreads();   // sN / sMm / sMloc complete

    // ---- class loss: one warp per matched cell ----
    int wid = tid >> 5, lane = tid & 31;
    int n = sN;
    for (int w = wid; w < n; w += 12) {
        int m = sMm[w];
        int idx = sMloc[w];
        int cls = (int)sPay[m][5];
        size_t cbase = ((size_t)(b * 255 + anc * 85 + 5)) * CELLS + idx;
        #pragma unroll
        for (int r = 0; r < 3; r++) {
            int cc = lane + r * 32;
            if (cc < NCc) {
                float z = __ldg(&out[cbase + (size_t)cc * CELLS]);
                float p = 1.f / (1.f + __expf(-z));
                float lp = fmaxf(__logf(p), -100.f);
                float lq = fmaxf(__logf(1.f - p), -100.f);
                float t = (cc == cls) ? 1.f : 0.f;
                a_cls += -(t * lp + (1.f - t) * lq);
                float e = p - t;
                a_l2 += e * e;
            }
        }
    }

    // ---- reduce: warp shuffle -> smem -> thread 0 -> double atomics ----
    unsigned msk = 0xffffffffu;
    for (int off = 16; off > 0; off >>= 1) {
        a_xy  += __shfl_down_sync(msk, a_xy, off);
        a_wh  += __shfl_down_sync(msk, a_wh, off);
        a_obj += __shfl_down_sync(msk, a_obj, off);
        a_cls += __shfl_down_sync(msk, a_cls, off);
        a_l2  += __shfl_down_sync(msk, a_l2, off);
    }
    if (lane == 0) {
        sRed[wid][0] = a_xy; sRed[wid][1] = a_wh; sRed[wid][2] = a_obj;
        sRed[wid][3] = a_cls; sRed[wid][4] = a_l2;
    }
    __syncthreads();
    if (tid == 0) {
        float r0 = 0.f, r1 = 0.f, r2 = 0.f, r3 = 0.f, r4 = 0.f;
        #pragma unroll
        for (int w = 0; w < 12; w++) {
            r0 += sRed[w][0]; r1 += sRed[w][1]; r2 += sRed[w][2];
            r3 += sRed[w][3]; r4 += sRed[w][4];
        }
        atomicAdd(&g_acc[1], (double)r0);
        atomicAdd(&g_acc[2], (double)r1);
        atomicAdd(&g_acc[3], (double)r2);
        atomicAdd(&g_acc[4], (double)r3);
        atomicAdd(&g_acc[5], (double)r4);
        __threadfence();
        int d = atomicAdd(&g_done, 1);
        if (d == NBLK - 1) {
            double xy = atomicAdd(&g_acc[1], 0.0);
            double wh = atomicAdd(&g_acc[2], 0.0);
            double ob = atomicAdd(&g_acc[3], 0.0);
            double cl = atomicAdd(&g_acc[4], 0.0);
            double l2 = atomicAdd(&g_acc[5], 0.0);
            o[0] = (float)(xy + wh + ob + cl);
            o[1] = (float)xy;
            o[2] = (float)wh;
            o[3] = (float)ob;
            o[4] = (float)cl;
            o[5] = (float)l2;
            g_acc[1] = 0.0; g_acc[2] = 0.0; g_acc[3] = 0.0;
            g_acc[4] = 0.0; g_acc[5] = 0.0;
            g_done = 0;
        }
    }
}

extern "C" void kernel_launch(void* const* d_in, const int* in_sizes, int n_in,
                              void* d_out, int out_size) {
    const float* output = (const float*)d_in[0];
    const float* labels = (const float*)d_in[1];
    float* o = (float*)d_out;
    (void)in_sizes; (void)n_in; (void)out_size;

    dim3 grid(BB, 3);
    k_fused<<<grid, 384>>>(output, labels, o);
}